// round 12
// baseline (speedup 1.0000x reference)
#include <cuda_runtime.h>

#define N_FFT   2048
#define L_SIG   1024
#define H_DIM   512
#define THREADS 128
#define TWO_PI  6.28318530717958647693f

// bank-conflict padding: one extra float2 per 16
#define PAD(i) ((i) + ((i) >> 4))
#define BUF_ELEMS (N_FFT + (N_FFT >> 4))   // 2176 float2 = 17.4 KB

__device__ float2 g_kf[H_DIM * N_FFT];   // 8 MB k-spectrum scratch

__device__ __forceinline__ float2 cadd(float2 a, float2 b){ return make_float2(a.x+b.x, a.y+b.y); }
__device__ __forceinline__ float2 csub(float2 a, float2 b){ return make_float2(a.x-b.x, a.y-b.y); }
__device__ __forceinline__ float2 cmul(float2 a, float2 b){
    return make_float2(a.x*b.x - a.y*b.y, a.x*b.y + a.y*b.x);
}
__device__ __forceinline__ float2 mul_negi(float2 a){ return make_float2(a.y, -a.x); } // a * (-i)

__device__ __forceinline__ void dft4(float2& x0, float2& x1, float2& x2, float2& x3){
    float2 t0 = cadd(x0,x2), t1 = csub(x0,x2);
    float2 t2 = cadd(x1,x3), t3 = csub(x1,x3);
    float2 it3 = mul_negi(t3);
    x0 = cadd(t0,t2);
    x1 = cadd(t1,it3);
    x2 = csub(t0,t2);
    x3 = csub(t1,it3);
}

// 8-point DFT, natural order in/out
__device__ __forceinline__ void dft8(float2 v[8]){
    const float c = 0.70710678118654752440f;
    float2 e0=v[0], e1=v[2], e2=v[4], e3=v[6];
    float2 o0=v[1], o1=v[3], o2=v[5], o3=v[7];
    dft4(e0,e1,e2,e3);
    dft4(o0,o1,o2,o3);
    float2 w1o = make_float2(c*(o1.x + o1.y), c*(o1.y - o1.x));   // o1 * W8^1
    float2 w2o = mul_negi(o2);                                    // o2 * W8^2
    float2 w3o = make_float2(c*(o3.y - o3.x), -c*(o3.x + o3.y));  // o3 * W8^3
    v[0]=cadd(e0,o0);  v[4]=csub(e0,o0);
    v[1]=cadd(e1,w1o); v[5]=csub(e1,w1o);
    v[2]=cadd(e2,w2o); v[6]=csub(e2,w2o);
    v[3]=cadd(e3,w3o); v[7]=csub(e3,w3o);
}

// 8-point DFT computing only outputs p=0..3 (into v[0..3])
__device__ __forceinline__ void dft8_half(float2 v[8]){
    const float c = 0.70710678118654752440f;
    float2 e0=v[0], e1=v[2], e2=v[4], e3=v[6];
    float2 o0=v[1], o1=v[3], o2=v[5], o3=v[7];
    dft4(e0,e1,e2,e3);
    dft4(o0,o1,o2,o3);
    float2 w1o = make_float2(c*(o1.x + o1.y), c*(o1.y - o1.x));
    float2 w2o = mul_negi(o2);
    float2 w3o = make_float2(c*(o3.y - o3.x), -c*(o3.x + o3.y));
    v[0]=cadd(e0,o0);
    v[1]=cadd(e1,w1o);
    v[2]=cadd(e2,w2o);
    v[3]=cadd(e3,w3o);
}

// 16-point DFT as 4x4. Natural input in v[0..15].
// OUTPUT PERMUTED: X[q + 4r] ends up in slot v[4q + r]  (use SLOT16 when storing).
// If ZP, inputs v[8..15] are treated as zero (not read).
#define SLOT16(p) (4*((p)&3) + ((p)>>2))
template<bool ZP>
__device__ __forceinline__ void dft16(float2 v[16]){
    const float c1 = 0.92387953251128675613f; // cos(pi/8)
    const float s1 = 0.38268343236508977173f; // sin(pi/8)
    const float r2 = 0.70710678118654752440f;
    #pragma unroll
    for (int b = 0; b < 4; b++){
        if (ZP) {
            float2 t0 = v[b], t1 = v[b+4];
            v[b]    = cadd(t0,t1);
            v[b+4]  = make_float2(t0.x + t1.y, t0.y - t1.x); // t0 - i*t1
            v[b+8]  = csub(t0,t1);
            v[b+12] = make_float2(t0.x - t1.y, t0.y + t1.x); // t0 + i*t1
        } else {
            dft4(v[b], v[b+4], v[b+8], v[b+12]);
        }
    }
    v[5]  = cmul(v[5],  make_float2(c1, -s1));   // W16^1
    v[9]  = cmul(v[9],  make_float2(r2, -r2));   // W16^2
    v[13] = cmul(v[13], make_float2(s1, -c1));   // W16^3
    v[6]  = cmul(v[6],  make_float2(r2, -r2));   // W16^2
    v[10] = mul_negi(v[10]);                     // W16^4
    v[14] = cmul(v[14], make_float2(-r2, -r2));  // W16^6
    v[7]  = cmul(v[7],  make_float2(s1, -c1));   // W16^3
    v[11] = cmul(v[11], make_float2(-r2, -r2));  // W16^6
    v[15] = cmul(v[15], make_float2(-c1, s1));   // W16^9
    #pragma unroll
    for (int q = 0; q < 4; q++)
        dft4(v[4*q], v[4*q+1], v[4*q+2], v[4*q+3]);
}

// 2048-pt FFT, radix 16*16*8 Stockham, 128 threads, 16 complex regs/thread.
// Input arrives in v[]: v[m] = x[tid + 128*m] (for ZPAD only m<8 used; rest zero).
// Result left in buf in natural order (PAD-indexed); trailing __syncthreads.
// If TRUNC, only outputs 0..1023 are computed/stored in the final pass.
template<bool ZPAD, bool TRUNC>
__device__ __forceinline__ void fft2048(float2* buf, float2 v[16], int tid){
    // ---- pass A: R=16, L=1 (no twiddles)
    dft16<ZPAD>(v);
    {
        int base = tid << 4;
        #pragma unroll
        for (int p = 0; p < 16; p++)
            buf[PAD(base + p)] = v[SLOT16(p)];
    }
    __syncthreads();
    // ---- pass B: R=16, L=16
    {
        #pragma unroll
        for (int m = 0; m < 16; m++) v[m] = buf[PAD(tid + (m<<7))];
        __syncthreads();
        int k = tid & 15;
        float s, c; __sincosf(-(float)k * (TWO_PI/256.f), &s, &c);
        float2 w1 = make_float2(c, s), w = w1;
        v[1] = cmul(v[1], w);
        #pragma unroll
        for (int m = 2; m < 16; m++){ w = cmul(w, w1); v[m] = cmul(v[m], w); }
        dft16<false>(v);
        int base = ((tid >> 4) << 8) + k;
        #pragma unroll
        for (int p = 0; p < 16; p++)
            buf[PAD(base + (p<<4))] = v[SLOT16(p)];
    }
    __syncthreads();
    // ---- pass C: R=8, L=256, two butterflies per thread (t = tid, tid+128)
    {
        #pragma unroll
        for (int m = 0; m < 8; m++) v[m]     = buf[PAD(tid       + (m<<8))];
        #pragma unroll
        for (int m = 0; m < 8; m++) v[8 + m] = buf[PAD(tid + 128 + (m<<8))];
        __syncthreads();
        float s, c;
        __sincosf(-(float)tid * (TWO_PI/2048.f), &s, &c);
        float2 w1 = make_float2(c, s), w = w1;
        v[1] = cmul(v[1], w);
        #pragma unroll
        for (int m = 2; m < 8; m++){ w = cmul(w, w1); v[m] = cmul(v[m], w); }
        int t1 = tid + 128;
        __sincosf(-(float)t1 * (TWO_PI/2048.f), &s, &c);
        float2 u1 = make_float2(c, s); w = u1;
        v[9] = cmul(v[9], w);
        #pragma unroll
        for (int m = 2; m < 8; m++){ w = cmul(w, u1); v[8+m] = cmul(v[8+m], w); }
        if (TRUNC) {
            dft8_half(v);
            dft8_half(v + 8);
            #pragma unroll
            for (int p = 0; p < 4; p++) buf[PAD(tid       + (p<<8))] = v[p];
            #pragma unroll
            for (int p = 0; p < 4; p++) buf[PAD(tid + 128 + (p<<8))] = v[8+p];
        } else {
            dft8(v);
            dft8(v + 8);
            #pragma unroll
            for (int p = 0; p < 8; p++) buf[PAD(tid       + (p<<8))] = v[p];
            #pragma unroll
            for (int p = 0; p < 8; p++) buf[PAD(tid + 128 + (p<<8))] = v[8+p];
        }
    }
    __syncthreads();
}

// One block per h: spectrum of zero-padded k row -> g_kf[h]
__global__ void __launch_bounds__(THREADS, 4) kf_kernel(const float* __restrict__ k) {
    __shared__ float2 buf[BUF_ELEMS];
    const int h = blockIdx.x;
    const int tid = threadIdx.x;
    const float* kr = k + (size_t)h * L_SIG;
    float2 v[16];
    #pragma unroll
    for (int m = 0; m < 8; m++) v[m] = make_float2(kr[tid + (m<<7)], 0.0f);

    fft2048<true, false>(buf, v, tid);

    float2* dst = g_kf + (size_t)h * N_FFT;
    #pragma unroll
    for (int m = 0; m < 16; m++) {
        int idx = tid + (m<<7);
        dst[idx] = buf[PAD(idx)];
    }
}

// One block per (h, batch-pair). z = u_b + i*u_{b+1}; IFFT(FFT(z)*K) = y_b + i*y_{b+1}
// (k real). IFFT(v) = conj(FFT(conj(v)))/N: FFT conj(z_f*K), read Re / -Im.
// kf row is prefetched into smem with cp.async at kernel start; the forward FFT
// hides its latency. __launch_bounds__(128, 5) caps regs at 102 (gentle — the
// live set is ~100, so minimal spill) giving 5 CTAs/SM = 29% occupancy.
__global__ void __launch_bounds__(THREADS, 5) conv_kernel(const float* __restrict__ u,
                                                          const float* __restrict__ D,
                                                          float* __restrict__ out) {
    __shared__ float2 buf[BUF_ELEMS];
    __shared__ float2 kbuf[N_FFT];          // 16 KB prefetched spectrum
    const int h   = blockIdx.x;   // 0..511
    const int bp  = blockIdx.y;   // 0..7
    const int tid = threadIdx.x;

    // ---- issue async prefetch of K_h (8 x 16B per thread), completes during fwd FFT
    {
        const float2* __restrict__ src = g_kf + (size_t)h * N_FFT;
        unsigned smem_base = (unsigned)__cvta_generic_to_shared(kbuf);
        #pragma unroll
        for (int r = 0; r < 8; r++) {
            int c = tid + (r<<7);            // 16B chunk index, 0..1023
            asm volatile("cp.async.cg.shared.global [%0], [%1], 16;"
                         :: "r"(smem_base + c*16), "l"(src + c*2));
        }
        asm volatile("cp.async.commit_group;");
    }

    const size_t row_stride = (size_t)H_DIM * L_SIG;
    const float* u0 = u + ((size_t)(2 * bp) * H_DIM + h) * L_SIG;
    const float* u1 = u0 + row_stride;

    float2 v[16];
    #pragma unroll
    for (int m = 0; m < 8; m++) {
        int idx = tid + (m<<7);
        v[m] = make_float2(u0[idx], u1[idx]);
    }

    fft2048<true, false>(buf, v, tid);

    // ---- pointwise: v = conj(Z * K) from smem
    asm volatile("cp.async.wait_group 0;");
    __syncthreads();
    #pragma unroll
    for (int m = 0; m < 16; m++) {
        int idx = tid + (m<<7);
        float2 z = buf[PAD(idx)];
        float2 K = kbuf[idx];
        v[m] = make_float2(z.x*K.x - z.y*K.y, -(z.x*K.y + z.y*K.x));
    }
    __syncthreads();   // all reads of buf done before pass-A writes

    fft2048<false, true>(buf, v, tid);

    const float d   = D[h];
    const float inv = 1.0f / (float)N_FFT;
    float* y0 = out + ((size_t)(2 * bp) * H_DIM + h) * L_SIG;
    float* y1 = y0 + row_stride;
    #pragma unroll
    for (int i = 0; i < 8; i++) {
        int idx = tid + (i<<7);
        float2 r = buf[PAD(idx)];
        y0[idx] =  r.x * inv + u0[idx] * d;   // L2-hot reload of u
        y1[idx] = -r.y * inv + u1[idx] * d;
    }
}

extern "C" void kernel_launch(void* const* d_in, const int* in_sizes, int n_in,
                              void* d_out, int out_size) {
    const float* u = (const float*)d_in[0];
    const float* k = (const float*)d_in[1];
    const float* D = (const float*)d_in[2];
    float* out = (float*)d_out;

    kf_kernel<<<H_DIM, THREADS>>>(k);
    conv_kernel<<<dim3(H_DIM, 8), THREADS>>>(u, D, out);
}

// round 13
// speedup vs baseline: 1.2179x; 1.2179x over previous
#include <cuda_runtime.h>

#define N_FFT   2048
#define L_SIG   1024
#define H_DIM   512
#define THREADS 128
#define TWO_PI  6.28318530717958647693f

// bank-conflict padding: one extra float2 per 16
#define PAD(i) ((i) + ((i) >> 4))
#define BUF_ELEMS (N_FFT + (N_FFT >> 4))   // 2176 float2 = 17.4 KB

__device__ float2 g_kf[H_DIM * N_FFT];   // 8 MB k-spectrum scratch

__device__ __forceinline__ float2 cadd(float2 a, float2 b){ return make_float2(a.x+b.x, a.y+b.y); }
__device__ __forceinline__ float2 csub(float2 a, float2 b){ return make_float2(a.x-b.x, a.y-b.y); }
__device__ __forceinline__ float2 cmul(float2 a, float2 b){
    return make_float2(a.x*b.x - a.y*b.y, a.x*b.y + a.y*b.x);
}
__device__ __forceinline__ float2 mul_negi(float2 a){ return make_float2(a.y, -a.x); } // a * (-i)

// slot map after the in-place pointwise: logical spectrum index m lives at v[HM(m)]
__device__ __forceinline__ constexpr int HM(int m){ return (m & 1) ? 8 + (m >> 1) : (m >> 1); }

__device__ __forceinline__ void dft4(float2& x0, float2& x1, float2& x2, float2& x3){
    float2 t0 = cadd(x0,x2), t1 = csub(x0,x2);
    float2 t2 = cadd(x1,x3), t3 = csub(x1,x3);
    float2 it3 = mul_negi(t3);
    x0 = cadd(t0,t2);
    x1 = cadd(t1,it3);
    x2 = csub(t0,t2);
    x3 = csub(t1,it3);
}

// 8-point DFT, natural order in/out
__device__ __forceinline__ void dft8(float2 v[8]){
    const float c = 0.70710678118654752440f;
    float2 e0=v[0], e1=v[2], e2=v[4], e3=v[6];
    float2 o0=v[1], o1=v[3], o2=v[5], o3=v[7];
    dft4(e0,e1,e2,e3);
    dft4(o0,o1,o2,o3);
    float2 w1o = make_float2(c*(o1.x + o1.y), c*(o1.y - o1.x));   // o1 * W8^1
    float2 w2o = mul_negi(o2);                                    // o2 * W8^2
    float2 w3o = make_float2(c*(o3.y - o3.x), -c*(o3.x + o3.y));  // o3 * W8^3
    v[0]=cadd(e0,o0);  v[4]=csub(e0,o0);
    v[1]=cadd(e1,w1o); v[5]=csub(e1,w1o);
    v[2]=cadd(e2,w2o); v[6]=csub(e2,w2o);
    v[3]=cadd(e3,w3o); v[7]=csub(e3,w3o);
}

// 8-point DFT computing only outputs p=0..3 (into v[0..3])
__device__ __forceinline__ void dft8_half(float2 v[8]){
    const float c = 0.70710678118654752440f;
    float2 e0=v[0], e1=v[2], e2=v[4], e3=v[6];
    float2 o0=v[1], o1=v[3], o2=v[5], o3=v[7];
    dft4(e0,e1,e2,e3);
    dft4(o0,o1,o2,o3);
    float2 w1o = make_float2(c*(o1.x + o1.y), c*(o1.y - o1.x));
    float2 w2o = mul_negi(o2);
    float2 w3o = make_float2(c*(o3.y - o3.x), -c*(o3.x + o3.y));
    v[0]=cadd(e0,o0);
    v[1]=cadd(e1,w1o);
    v[2]=cadd(e2,w2o);
    v[3]=cadd(e3,w3o);
}

// 16-point DFT as 4x4. Logical input index m is read from v[PERM ? HM(m) : m].
// OUTPUT PERMUTED: X[q + 4r] ends up in logical slot 4q + r (same mapping applied).
// If ZP, logical inputs 8..15 are treated as zero (not read).
#define SLOT16(p) (4*((p)&3) + ((p)>>2))
template<bool ZP, bool PERM>
__device__ __forceinline__ void dft16(float2 v[16]){
    const float c1 = 0.92387953251128675613f; // cos(pi/8)
    const float s1 = 0.38268343236508977173f; // sin(pi/8)
    const float r2 = 0.70710678118654752440f;
#define VV(m) v[PERM ? HM(m) : (m)]
    #pragma unroll
    for (int b = 0; b < 4; b++){
        if (ZP) {
            float2 t0 = VV(b), t1 = VV(b+4);
            VV(b)    = cadd(t0,t1);
            VV(b+4)  = make_float2(t0.x + t1.y, t0.y - t1.x); // t0 - i*t1
            VV(b+8)  = csub(t0,t1);
            VV(b+12) = make_float2(t0.x - t1.y, t0.y + t1.x); // t0 + i*t1
        } else {
            dft4(VV(b), VV(b+4), VV(b+8), VV(b+12));
        }
    }
    VV(5)  = cmul(VV(5),  make_float2(c1, -s1));   // W16^1
    VV(9)  = cmul(VV(9),  make_float2(r2, -r2));   // W16^2
    VV(13) = cmul(VV(13), make_float2(s1, -c1));   // W16^3
    VV(6)  = cmul(VV(6),  make_float2(r2, -r2));   // W16^2
    VV(10) = mul_negi(VV(10));                     // W16^4
    VV(14) = cmul(VV(14), make_float2(-r2, -r2));  // W16^6
    VV(7)  = cmul(VV(7),  make_float2(s1, -c1));   // W16^3
    VV(11) = cmul(VV(11), make_float2(-r2, -r2));  // W16^6
    VV(15) = cmul(VV(15), make_float2(-c1, s1));   // W16^9
    #pragma unroll
    for (int q = 0; q < 4; q++)
        dft4(VV(4*q), VV(4*q+1), VV(4*q+2), VV(4*q+3));
#undef VV
}

// Passes A and B of the 2048-pt radix 16*16*8 Stockham (128 thr, 16 regs).
// Logical input: x[tid + 128*m] at v-slot (PERM ? HM(m) : m).
// Leaves pass-B result in buf; ends with a __syncthreads.
template<bool ZPAD, bool PERM>
__device__ __forceinline__ void fft_AB(float2* buf, float2 v[16], int tid){
    // ---- pass A: R=16, L=1 (no twiddles)
    dft16<ZPAD, PERM>(v);
    {
        int base = tid << 4;
        #pragma unroll
        for (int p = 0; p < 16; p++)
            buf[PAD(base + p)] = v[PERM ? HM(SLOT16(p)) : SLOT16(p)];
    }
    __syncthreads();
    // ---- pass B: R=16, L=16 (natural slots from here on)
    #pragma unroll
    for (int m = 0; m < 16; m++) v[m] = buf[PAD(tid + (m<<7))];
    __syncthreads();
    {
        int k = tid & 15;
        float s, c; __sincosf(-(float)k * (TWO_PI/256.f), &s, &c);
        float2 w1 = make_float2(c, s), w = w1;
        v[1] = cmul(v[1], w);
        #pragma unroll
        for (int m = 2; m < 16; m++){ w = cmul(w, w1); v[m] = cmul(v[m], w); }
        dft16<false, false>(v);
        int base = ((tid >> 4) << 8) + k;
        #pragma unroll
        for (int p = 0; p < 16; p++)
            buf[PAD(base + (p<<4))] = v[SLOT16(p)];
    }
    __syncthreads();
}

// Pass C loads: v[0..7] <- butterfly at t=tid, v[8..15] <- t=tid+128
__device__ __forceinline__ void passC_load(const float2* buf, float2 v[16], int tid){
    #pragma unroll
    for (int m = 0; m < 8; m++) v[m]     = buf[PAD(tid       + (m<<8))];
    #pragma unroll
    for (int m = 0; m < 8; m++) v[8 + m] = buf[PAD(tid + 128 + (m<<8))];
}

// Pass C twiddle for butterfly index t: v[m] *= W2048^{t*m}
__device__ __forceinline__ void passC_twiddle(float2 v[8], int t){
    float s, c;
    __sincosf(-(float)t * (TWO_PI/2048.f), &s, &c);
    float2 w1 = make_float2(c, s), w = w1;
    v[1] = cmul(v[1], w);
    #pragma unroll
    for (int m = 2; m < 8; m++){ w = cmul(w, w1); v[m] = cmul(v[m], w); }
}

// One block per h: spectrum of zero-padded k row -> g_kf[h]
// Pass C result goes straight from registers to gmem (coalesced).
__global__ void __launch_bounds__(THREADS, 4) kf_kernel(const float* __restrict__ k) {
    __shared__ float2 buf[BUF_ELEMS];
    const int h = blockIdx.x;
    const int tid = threadIdx.x;
    const float* kr = k + (size_t)h * L_SIG;
    float2 v[16];
    #pragma unroll
    for (int m = 0; m < 8; m++) v[m] = make_float2(kr[tid + (m<<7)], 0.0f);

    fft_AB<true, false>(buf, v, tid);
    passC_load(buf, v, tid);
    passC_twiddle(v, tid);           dft8(v);
    passC_twiddle(v + 8, tid + 128); dft8(v + 8);

    float2* dst = g_kf + (size_t)h * N_FFT;
    #pragma unroll
    for (int p = 0; p < 8; p++) {
        dst[tid       + (p<<8)] = v[p];
        dst[tid + 128 + (p<<8)] = v[8 + p];
    }
}

// One block per (h, batch-pair). z = u_b + i*u_{b+1}; IFFT(FFT(z)*K) = y_b + i*y_{b+1}
// (k real). IFFT(v) = conj(FFT(conj(v)))/N: FFT conj(z_f*K), read Re / -Im.
// Fusion + prefetch: K_h is cp.async'd into smem at kernel start (latency hidden
// under the forward FFT), so the register-fused pointwise between forward pass C
// and inverse pass A reads 29-cyc smem, not gmem. The slot permutation from the
// in-place multiply is folded into inverse pass A as a compile-time map (PERM).
// Inverse pass C writes y directly from registers to gmem.
__global__ void __launch_bounds__(THREADS, 4) conv_kernel(const float* __restrict__ u,
                                                          const float* __restrict__ D,
                                                          float* __restrict__ out) {
    __shared__ float2 buf[BUF_ELEMS];
    __shared__ float2 kbuf[N_FFT];          // 16 KB prefetched spectrum
    const int h   = blockIdx.x;   // 0..511
    const int bp  = blockIdx.y;   // 0..7
    const int tid = threadIdx.x;

    // ---- issue async prefetch of K_h (8 x 16B per thread), completes during fwd FFT
    {
        const float2* __restrict__ src = g_kf + (size_t)h * N_FFT;
        unsigned smem_base = (unsigned)__cvta_generic_to_shared(kbuf);
        #pragma unroll
        for (int r = 0; r < 8; r++) {
            int c = tid + (r<<7);            // 16B chunk index, 0..1023
            asm volatile("cp.async.cg.shared.global [%0], [%1], 16;"
                         :: "r"(smem_base + c*16), "l"(src + c*2));
        }
        asm volatile("cp.async.commit_group;");
    }

    const size_t row_stride = (size_t)H_DIM * L_SIG;
    const float* u0 = u + ((size_t)(2 * bp) * H_DIM + h) * L_SIG;
    const float* u1 = u0 + row_stride;

    float2 v[16];
    #pragma unroll
    for (int m = 0; m < 8; m++) {
        int idx = tid + (m<<7);
        v[m] = make_float2(u0[idx], u1[idx]);
    }

    // ---- forward FFT: passes A,B in smem, pass C in registers
    fft_AB<true, false>(buf, v, tid);
    passC_load(buf, v, tid);
    passC_twiddle(v, tid);           dft8(v);
    passC_twiddle(v + 8, tid + 128); dft8(v + 8);

    // ---- fused pointwise IN PLACE from smem kbuf: v[p] holds Z[tid+256p],
    //      v[8+p] holds Z[tid+128+256p]. Afterwards logical spectrum index m
    //      sits at slot HM(m). Conflict-free LDS (consecutive lanes).
    asm volatile("cp.async.wait_group 0;");
    #pragma unroll
    for (int p = 0; p < 8; p++) {
        float2 K0 = kbuf[tid       + (p<<8)];
        float2 z0 = v[p];
        v[p]     = make_float2(z0.x*K0.x - z0.y*K0.y, -(z0.x*K0.y + z0.y*K0.x));
        float2 K1 = kbuf[tid + 128 + (p<<8)];
        float2 z1 = v[8 + p];
        v[8 + p] = make_float2(z1.x*K1.x - z1.y*K1.y, -(z1.x*K1.y + z1.y*K1.x));
    }
    __syncthreads();   // all fwd-C reads of buf done before inv-A writes

    // ---- inverse FFT: pass A reads through HM, passes B/C natural, truncated
    fft_AB<false, true>(buf, v, tid);
    passC_load(buf, v, tid);
    passC_twiddle(v, tid);           dft8_half(v);
    passC_twiddle(v + 8, tid + 128); dft8_half(v + 8);

    // ---- epilogue: y direct from registers (indices {tid,tid+128}+256p, p<4)
    const float d   = D[h];
    const float inv = 1.0f / (float)N_FFT;
    float* y0 = out + ((size_t)(2 * bp) * H_DIM + h) * L_SIG;
    float* y1 = y0 + row_stride;
    #pragma unroll
    for (int p = 0; p < 4; p++) {
        int i0 = tid + (p<<8);
        int i1 = tid + 128 + (p<<8);
        float2 r0 = v[p];
        float2 r1 = v[8 + p];
        y0[i0] =  r0.x * inv + u0[i0] * d;
        y1[i0] = -r0.y * inv + u1[i0] * d;
        y0[i1] =  r1.x * inv + u0[i1] * d;
        y1[i1] = -r1.y * inv + u1[i1] * d;
    }
}

extern "C" void kernel_launch(void* const* d_in, const int* in_sizes, int n_in,
                              void* d_out, int out_size) {
    const float* u = (const float*)d_in[0];
    const float* k = (const float*)d_in[1];
    const float* D = (const float*)d_in[2];
    float* out = (float*)d_out;

    kf_kernel<<<H_DIM, THREADS>>>(k);
    conv_kernel<<<dim3(H_DIM, 8), THREADS>>>(u, D, out);
}